// round 9
// baseline (speedup 1.0000x reference)
#include <cuda_runtime.h>
#include <cuda_fp16.h>
#include <math.h>
#include <stdint.h>

// ---------------- problem constants ----------------
constexpr int N_ = 1024;
constexpr int P_ = 523776;          // N*(N-1)/2
constexpr int TI = 32;              // pair tile dim
constexpr int NT = N_ / TI;         // 32 tiles per dim
constexpr int NBLK = NT * (NT + 1) / 2;  // 528 tiles over upper triangle
constexpr int UVS = 132;            // Us/Vs row stride (conflict-free float4)

// pair-kernel smem layout
// bytes [0, 32768):        Ht buf0 fp16 [128 rows][256 B] (XOR-swizzled 16B chunks)
// bytes [32768, 65536):    Ht buf1
// bytes [65536, 81920):    Wt fp16 [COLS<=64 rows][256 B]
constexpr int OFF_RED  = 20480;              // [2][512] epilogue partials (double buffer)
constexpr int OFF_STAT = OFF_RED + 1024;     // [512] LN stats
constexpr int OFF_US   = OFF_STAT + 512;     // [32][132]
constexpr int OFF_VS   = OFF_US + 32 * UVS;  // [32][132]
constexpr int OFF_B2   = OFF_VS + 32 * UVS;  // [64]
constexpr int OFF_W3   = OFF_B2 + 64;        // [64]
constexpr int OFF_LNG  = OFF_W3 + 64;        // [128]
constexpr int OFF_LNB  = OFF_LNG + 128;      // [128]
constexpr int SMEM_FLOATS = OFF_LNB + 128;
constexpr int SMEM_BYTES = SMEM_FLOATS * 4;  // ~121 KB

// precompute-kernel smem
constexpr int PRE_ES_STRIDE = 132;
constexpr int PRE_WS_STRIDE = 68;
constexpr int PRE_OFF_WS = 32 * PRE_ES_STRIDE;
constexpr int PRE_SMEM_BYTES = (PRE_OFF_WS + 128 * PRE_WS_STRIDE) * 4;

// ---------------- device scratch ----------------
__device__ float g_Uc[N_ * 128];
__device__ float g_Vc[N_ * 128];
__device__ float g_Ua[N_ * 128];
__device__ float g_Va[N_ * 128];

// ---------------- helpers ----------------
__device__ __forceinline__ float gelu_f(float x) {
    float u = 0.79788456080286536f * fmaf(0.044715f * x, x * x, x);
    float th;
    asm("tanh.approx.f32 %0, %1;" : "=f"(th) : "f"(u));
    return 0.5f * x * (1.0f + th);
}
__device__ __forceinline__ float sigmoid_f(float x) {
    return 1.0f / (1.0f + expf(-x));
}
__device__ __forceinline__ uint32_t smem_u32(const void* p) {
    uint32_t a;
    asm("{ .reg .u64 t; cvta.to.shared.u64 t, %1; cvt.u32.u64 %0, t; }" : "=r"(a) : "l"(p));
    return a;
}
__device__ __forceinline__ void ldsm_x4(uint32_t& r0, uint32_t& r1, uint32_t& r2, uint32_t& r3,
                                        uint32_t addr) {
    asm volatile("ldmatrix.sync.aligned.m8n8.x4.shared.b16 {%0,%1,%2,%3}, [%4];"
                 : "=r"(r0), "=r"(r1), "=r"(r2), "=r"(r3) : "r"(addr));
}
__device__ __forceinline__ void ldsm_x2(uint32_t& r0, uint32_t& r1, uint32_t addr) {
    asm volatile("ldmatrix.sync.aligned.m8n8.x2.shared.b16 {%0,%1}, [%2];"
                 : "=r"(r0), "=r"(r1) : "r"(addr));
}
__device__ __forceinline__ void mma16816(float* c, uint32_t a0, uint32_t a1, uint32_t a2,
                                         uint32_t a3, uint32_t b0, uint32_t b1) {
    asm volatile(
        "mma.sync.aligned.m16n8k16.row.col.f32.f16.f16.f32 "
        "{%0,%1,%2,%3}, {%4,%5,%6,%7}, {%8,%9}, {%0,%1,%2,%3};"
        : "+f"(c[0]), "+f"(c[1]), "+f"(c[2]), "+f"(c[3])
        : "r"(a0), "r"(a1), "r"(a2), "r"(a3), "r"(b0), "r"(b1));
}
__device__ __forceinline__ uint4 pack8h(const float* h) {
    __half2 p0 = __floats2half2_rn(h[0], h[1]);
    __half2 p1 = __floats2half2_rn(h[2], h[3]);
    __half2 p2 = __floats2half2_rn(h[4], h[5]);
    __half2 p3 = __floats2half2_rn(h[6], h[7]);
    uint4 r;
    r.x = *reinterpret_cast<uint32_t*>(&p0);
    r.y = *reinterpret_cast<uint32_t*>(&p1);
    r.z = *reinterpret_cast<uint32_t*>(&p2);
    r.w = *reinterpret_cast<uint32_t*>(&p3);
    return r;
}

// ---------------- kernel 1: precompute tiled GEMM ----------------
__global__ void __launch_bounds__(256) precompute_gemm_kernel(
    const float* __restrict__ E,
    const float* __restrict__ cW1, const float* __restrict__ cb1,
    const float* __restrict__ aW1, const float* __restrict__ ab1)
{
    extern __shared__ float psm[];
    float* Es = psm;
    float* Ws = psm + PRE_OFF_WS;

    int rowTile = blockIdx.x >> 3;
    int colTile = blockIdx.x & 7;
    int arr = colTile >> 1;
    int c0 = (colTile & 1) * 64;
    int r0 = rowTile * 32;

    const float* Wsrc = (arr < 2) ? cW1 : aW1;
    int doff = (arr & 1) ? 128 : 0;

    int t = threadIdx.x;
    for (int x = t; x < 32 * 32; x += 256) {
        int r = x >> 5, k4 = x & 31;
        float4 e = *reinterpret_cast<const float4*>(E + (r0 + r) * 128 + k4 * 4);
        *reinterpret_cast<float4*>(Es + r * PRE_ES_STRIDE + k4 * 4) = e;
    }
    for (int x = t; x < 128 * 16; x += 256) {
        int d = x >> 4, c4 = x & 15;
        float4 w = *reinterpret_cast<const float4*>(Wsrc + (doff + d) * 128 + c0 + c4 * 4);
        *reinterpret_cast<float4*>(Ws + d * PRE_WS_STRIDE + c4 * 4) = w;
    }
    __syncthreads();

    int cgr = t & 15;
    int rg  = t >> 4;
    float acc[2][4] = {};

#pragma unroll 4
    for (int k = 0; k < 128; k += 4) {
        float4 ev[2], wv[4];
#pragma unroll
        for (int i = 0; i < 2; i++)
            ev[i] = *reinterpret_cast<const float4*>(Es + (rg * 2 + i) * PRE_ES_STRIDE + k);
#pragma unroll
        for (int kk = 0; kk < 4; kk++)
            wv[kk] = *reinterpret_cast<const float4*>(Ws + (k + kk) * PRE_WS_STRIDE + cgr * 4);
#pragma unroll
        for (int i = 0; i < 2; i++) {
            float er[4] = {ev[i].x, ev[i].y, ev[i].z, ev[i].w};
#pragma unroll
            for (int kk = 0; kk < 4; kk++) {
                acc[i][0] = fmaf(er[kk], wv[kk].x, acc[i][0]);
                acc[i][1] = fmaf(er[kk], wv[kk].y, acc[i][1]);
                acc[i][2] = fmaf(er[kk], wv[kk].z, acc[i][2]);
                acc[i][3] = fmaf(er[kk], wv[kk].w, acc[i][3]);
            }
        }
    }

    float* dst = (arr == 0) ? g_Uc : (arr == 1) ? g_Vc : (arr == 2) ? g_Ua : g_Va;
    float4 bias = make_float4(0.f, 0.f, 0.f, 0.f);
    if (arr == 0) bias = *reinterpret_cast<const float4*>(cb1 + c0 + cgr * 4);
    if (arr == 2) bias = *reinterpret_cast<const float4*>(ab1 + c0 + cgr * 4);
#pragma unroll
    for (int i = 0; i < 2; i++) {
        float4 o;
        o.x = acc[i][0] + bias.x; o.y = acc[i][1] + bias.y;
        o.z = acc[i][2] + bias.z; o.w = acc[i][3] + bias.w;
        *reinterpret_cast<float4*>(dst + (r0 + rg * 2 + i) * 128 + c0 + cgr * 4) = o;
    }
}

// ---------------- importance body (blocks 0..7) ----------------
__device__ __forceinline__ void imp_body(
    int bid, float* sm,
    const float* __restrict__ E, const float* __restrict__ trace,
    const float* __restrict__ iW1, const float* __restrict__ ib1,
    const float* __restrict__ iW2, const float* __restrict__ ib2,
    float* __restrict__ outb)
{
    int t = threadIdx.x;
    float* Ws = sm;                        // [133][64]
    for (int x = t; x < 133 * 64; x += 512) Ws[x] = iW1[x];
    __syncthreads();

    int row = bid * 128 + (t >> 2);
    int c0 = (t & 3) * 16;
    float acc[16];
#pragma unroll
    for (int i = 0; i < 16; i++) acc[i] = ib1[c0 + i];

    const float* erow = E + row * 128;
    for (int d4 = 0; d4 < 32; d4++) {
        float4 e4 = *reinterpret_cast<const float4*>(erow + d4 * 4);
        float ev[4] = {e4.x, e4.y, e4.z, e4.w};
#pragma unroll
        for (int dd = 0; dd < 4; dd++) {
            const float* wrow = Ws + (d4 * 4 + dd) * 64 + c0;
            float4 w0 = *reinterpret_cast<const float4*>(wrow);
            float4 w1 = *reinterpret_cast<const float4*>(wrow + 4);
            float4 w2 = *reinterpret_cast<const float4*>(wrow + 8);
            float4 w3 = *reinterpret_cast<const float4*>(wrow + 12);
            float e = ev[dd];
            acc[0]  = fmaf(e, w0.x, acc[0]);  acc[1]  = fmaf(e, w0.y, acc[1]);
            acc[2]  = fmaf(e, w0.z, acc[2]);  acc[3]  = fmaf(e, w0.w, acc[3]);
            acc[4]  = fmaf(e, w1.x, acc[4]);  acc[5]  = fmaf(e, w1.y, acc[5]);
            acc[6]  = fmaf(e, w1.z, acc[6]);  acc[7]  = fmaf(e, w1.w, acc[7]);
            acc[8]  = fmaf(e, w2.x, acc[8]);  acc[9]  = fmaf(e, w2.y, acc[9]);
            acc[10] = fmaf(e, w2.z, acc[10]); acc[11] = fmaf(e, w2.w, acc[11]);
            acc[12] = fmaf(e, w3.x, acc[12]); acc[13] = fmaf(e, w3.y, acc[13]);
            acc[14] = fmaf(e, w3.z, acc[14]); acc[15] = fmaf(e, w3.w, acc[15]);
        }
    }
    for (int d5 = 0; d5 < 5; d5++) {
        float e = trace[row * 5 + d5];
        const float* wrow = Ws + (128 + d5) * 64 + c0;
#pragma unroll
        for (int i = 0; i < 16; i++) acc[i] = fmaf(e, wrow[i], acc[i]);
    }
    float part = 0.f;
#pragma unroll
    for (int i = 0; i < 16; i++) part = fmaf(gelu_f(acc[i]), iW2[c0 + i], part);
    part += __shfl_xor_sync(0xffffffffu, part, 1);
    part += __shfl_xor_sync(0xffffffffu, part, 2);
    if ((t & 3) == 0) outb[row] = sigmoid_f(part + ib2[0]);
}

// ---------------- pair MLP body: warp-specialized pipeline ----------------
// warps 0..7 = GEMM consumers (M=64 x N=COLS/4 each, 2 m-ranges x 4 n-ranges);
// warps 8..15 = phase-A producers (2 threads/pair over 128-pair chunks);
// 8 chunks, double-buffered Ht, producers also do the (it-2) combine/store.
template <int COLS, bool IS_CONS>
__device__ __forceinline__ void pair_body(
    int bid, float* sm,
    const float* __restrict__ Ug, const float* __restrict__ Vg,
    const float* __restrict__ W2g, const float* __restrict__ b2g,
    const float* __restrict__ w3g, const float* __restrict__ b3g,
    const float* __restrict__ lng, const float* __restrict__ lnb,
    float* __restrict__ outb)
{
    constexpr int NW = COLS / 4;       // cols per consumer warp (16 / 8)
    constexpr int NTL = NW / 8;        // n-tiles per warp (2 / 1)

    float* red  = sm + OFF_RED;        // [2][512]
    float* stat = sm + OFF_STAT;       // [512]
    float* Us   = sm + OFF_US;
    float* Vs   = sm + OFF_VS;
    float* b2s  = sm + OFF_B2;
    float* w3s  = sm + OFF_W3;
    float* lngs = sm + OFF_LNG;
    float* lnbs = sm + OFF_LNB;
    char*  smc  = reinterpret_cast<char*>(sm);
    uint32_t base_u32 = smem_u32(sm);
    uint32_t WBASE = base_u32 + 65536;

    int t = threadIdx.x;
    int wid = t >> 5;
    int lane = t & 31;

    // decode bid -> (ti, tj), tj >= ti
    int rem = bid, ti = 0;
    while (rem >= NT - ti) { rem -= NT - ti; ti++; }
    int tj = ti + rem;
    int I0 = ti * TI, J0 = tj * TI;

    // ---- one-time smem fills (all threads) ----
    for (int x = t; x < COLS * 16; x += 512) {
        int n = x >> 4, j = x & 15;
        float w[8];
#pragma unroll
        for (int kk = 0; kk < 8; kk++) w[kk] = W2g[(j * 8 + kk) * COLS + n];
        uint4 pk = pack8h(w);
        *reinterpret_cast<uint4*>(smc + 65536 + n * 256 + ((j ^ (n & 7)) << 4)) = pk;
    }
    if (t < COLS) { b2s[t] = b2g[t]; w3s[t] = w3g[t]; }
    if constexpr (IS_CONS) {
        if (t >= 256 && t < 384) { lngs[t - 256] = lng[t - 256]; lnbs[t - 256] = lnb[t - 256]; }
    }
    for (int x = t; x < 32 * 128; x += 512) {
        int r = x >> 7, k = x & 127;
        Us[r * UVS + k] = Ug[(I0 + r) * 128 + k];
        Vs[r * UVS + k] = Vg[(J0 + r) * 128 + k];
    }
    float b3 = b3g[0];
    __syncthreads();

    // ---- consumer state ----
    int m0 = 0, n0 = 0, nrange = 0, g = 0, tid4 = 0, roff = 0;
    uint32_t bfr[8][2 * NTL];
    uint32_t a_sw[8];
    if (wid < 8) {
        m0 = (wid & 1) * 64;
        nrange = wid >> 1;
        n0 = nrange * NW;
        g = lane >> 2; tid4 = lane & 3;
        if constexpr (NTL == 2) {
            int nb = n0 + ((lane >> 4) & 1) * 8 + (lane & 7);
#pragma unroll
            for (int s = 0; s < 8; s++) {
                uint32_t addr = WBASE + nb * 256 +
                                (((2 * s + ((lane >> 3) & 1)) ^ (lane & 7)) << 4);
                ldsm_x4(bfr[s][0], bfr[s][1], bfr[s][2], bfr[s][3], addr);
            }
        } else {
            int nb = n0 + (lane & 7);
#pragma unroll
            for (int s = 0; s < 8; s++) {
                uint32_t addr = WBASE + nb * 256 +
                                (((2 * s + ((lane >> 3) & 1)) ^ (lane & 7)) << 4);
                ldsm_x2(bfr[s][0], bfr[s][1], addr);
            }
        }
        roff = ((lane >> 3) & 1) * 8 + (lane & 7);
#pragma unroll
        for (int s = 0; s < 8; s++)
            a_sw[s] = (uint32_t)(((2 * s + (lane >> 4)) ^ (lane & 7)) << 4);
    }

    // ---- producer state ----
    int t2 = t - 256;                 // valid for wid >= 8
    int p = t2 & 127, half = t2 >> 7;
    int k0 = half * 64;
    const float* vrow = Vs + (p & 31) * UVS + k0;

    // ---- pipeline: 10 iterations ----
    for (int it = 0; it < 10; it++) {
        if (wid < 8) {
            // ===== consumer: mma chunk it-1 =====
            if (it >= 1 && it <= 8) {
                int cbuf = (it - 1) & 1;
                uint32_t a_base = base_u32 + (uint32_t)(cbuf << 15) + (m0 + roff) * 256;
                float acc[4][NTL][4];
#pragma unroll
                for (int mt = 0; mt < 4; mt++)
#pragma unroll
                    for (int nt = 0; nt < NTL; nt++)
#pragma unroll
                        for (int q = 0; q < 4; q++) acc[mt][nt][q] = 0.f;
#pragma unroll
                for (int s = 0; s < 8; s++) {
#pragma unroll
                    for (int mt = 0; mt < 4; mt++) {
                        uint32_t a0, a1, a2, a3;
                        ldsm_x4(a0, a1, a2, a3, a_base + mt * 4096 + a_sw[s]);
                        mma16816(acc[mt][0], a0, a1, a2, a3, bfr[s][0], bfr[s][1]);
                        if constexpr (NTL == 2)
                            mma16816(acc[mt][1], a0, a1, a2, a3, bfr[s][2], bfr[s][3]);
                    }
                }
                // epilogue -> red[cbuf]
                float* rb = red + cbuf * 512;
#pragma unroll
                for (int mt = 0; mt < 4; mt++) {
                    float pr0 = 0.f, pr1 = 0.f;
#pragma unroll
                    for (int nt = 0; nt < NTL; nt++) {
                        int c0 = n0 + nt * 8 + 2 * tid4;
                        float w30 = w3s[c0], w31 = w3s[c0 + 1];
                        float bb0 = b2s[c0], bb1 = b2s[c0 + 1];
                        float y00 = acc[mt][nt][0] + bb0;
                        float y01 = acc[mt][nt][1] + bb1;
                        float y10 = acc[mt][nt][2] + bb0;
                        float y11 = acc[mt][nt][3] + bb1;
                        if constexpr (IS_CONS) {
                            pr0 = fmaf(gelu_f(y00), w30, pr0);
                            pr0 = fmaf(gelu_f(y01), w31, pr0);
                            pr1 = fmaf(gelu_f(y10), w30, pr1);
                            pr1 = fmaf(gelu_f(y11), w31, pr1);
                        } else {
                            pr0 = fmaf(fmaxf(y00, 0.f), w30, pr0);
                            pr0 = fmaf(fmaxf(y01, 0.f), w31, pr0);
                            pr1 = fmaf(fmaxf(y10, 0.f), w30, pr1);
                            pr1 = fmaf(fmaxf(y11, 0.f), w31, pr1);
                        }
                    }
                    pr0 += __shfl_xor_sync(0xffffffffu, pr0, 1);
                    pr0 += __shfl_xor_sync(0xffffffffu, pr0, 2);
                    pr1 += __shfl_xor_sync(0xffffffffu, pr1, 1);
                    pr1 += __shfl_xor_sync(0xffffffffu, pr1, 2);
                    if (tid4 == 0) {
                        rb[nrange * 128 + m0 + mt * 16 + g]     = pr0;
                        rb[nrange * 128 + m0 + mt * 16 + 8 + g] = pr1;
                    }
                }
            }
        } else {
            // ===== producer: phase A chunk it =====
            if (it < 8) {
                const float* urow = Us + (it * 4 + (p >> 5)) * UVS + k0;
                char* hb = smc + ((it & 1) << 15) + p * 256;
                if constexpr (IS_CONS) {
                    float4 xv[16];
                    float s1 = 0.f, s2 = 0.f;
#pragma unroll
                    for (int kk = 0; kk < 16; kk++) {
                        float4 uu = *reinterpret_cast<const float4*>(urow + kk * 4);
                        float4 vv = *reinterpret_cast<const float4*>(vrow + kk * 4);
                        float4 x;
                        x.x = uu.x + vv.x; x.y = uu.y + vv.y;
                        x.z = uu.z + vv.z; x.w = uu.w + vv.w;
                        xv[kk] = x;
                        s1 += (x.x + x.y) + (x.z + x.w);
                        s2 = fmaf(x.x, x.x, s2); s2 = fmaf(x.y, x.y, s2);
                        s2 = fmaf(x.z, x.z, s2); s2 = fmaf(x.w, x.w, s2);
                    }
                    stat[half * 128 + p] = s1;
                    stat[256 + half * 128 + p] = s2;
                    asm volatile("bar.sync 1, 256;" ::: "memory");
                    float s1t = stat[p] + stat[128 + p];
                    float s2t = stat[256 + p] + stat[384 + p];
                    float mean = s1t * 0.0078125f;
                    float var  = s2t * 0.0078125f - mean * mean;
                    float rstd = rsqrtf(var + 1e-5f);
#pragma unroll
                    for (int j = 0; j < 8; j++) {
                        float4 a = xv[2 * j], b = xv[2 * j + 1];
                        float xs[8] = {a.x, a.y, a.z, a.w, b.x, b.y, b.z, b.w};
                        float hs[8];
#pragma unroll
                        for (int i2 = 0; i2 < 8; i2++) {
                            int k = k0 + j * 8 + i2;
                            float hn = fmaf((xs[i2] - mean) * rstd, lngs[k], lnbs[k]);
                            hs[i2] = gelu_f(hn);
                        }
                        uint4 pk = pack8h(hs);
                        *reinterpret_cast<uint4*>(hb + (((half * 8 + j) ^ (p & 7)) << 4)) = pk;
                    }
                } else {
#pragma unroll
                    for (int j = 0; j < 8; j++) {
                        float4 uu0 = *reinterpret_cast<const float4*>(urow + j * 8);
                        float4 vv0 = *reinterpret_cast<const float4*>(vrow + j * 8);
                        float4 uu1 = *reinterpret_cast<const float4*>(urow + j * 8 + 4);
                        float4 vv1 = *reinterpret_cast<const float4*>(vrow + j * 8 + 4);
                        float hs[8] = {fmaxf(uu0.x + vv0.x, 0.f), fmaxf(uu0.y + vv0.y, 0.f),
                                       fmaxf(uu0.z + vv0.z, 0.f), fmaxf(uu0.w + vv0.w, 0.f),
                                       fmaxf(uu1.x + vv1.x, 0.f), fmaxf(uu1.y + vv1.y, 0.f),
                                       fmaxf(uu1.z + vv1.z, 0.f), fmaxf(uu1.w + vv1.w, 0.f)};
                        uint4 pk = pack8h(hs);
                        *reinterpret_cast<uint4*>(hb + (((half * 8 + j) ^ (p & 7)) << 4)) = pk;
                    }
                }
            }
            // ===== producer: combine chunk it-2 =====
            if (it >= 2 && t2 < 128) {
                int c = it - 2;
                float* rb = red + (c & 1) * 512;
                float logit = b3 + ((rb[t2] + rb[128 + t2]) + (rb[256 + t2] + rb[384 + t2]));
                int i = I0 + c * 4 + (t2 >> 5), j = J0 + (t2 & 31);
                if (i < j) {
                    int pidx = i * (N_ - 1) - (i * (i - 1)) / 2 + (j - i - 1);
                    outb[pidx] = sigmoid_f(logit);
                }
            }
        }
        __syncthreads();
    }
}

// ---------------- fused kernel: imp [0,8), cons [8,536), assoc [536,1064) ----------------
__global__ void __launch_bounds__(512, 1) pair_fused_kernel(
    const float* __restrict__ cW2, const float* __restrict__ cb2,
    const float* __restrict__ cW3, const float* __restrict__ cb3,
    const float* __restrict__ lng, const float* __restrict__ lnb,
    const float* __restrict__ aW2, const float* __restrict__ ab2,
    const float* __restrict__ aW3, const float* __restrict__ ab3,
    const float* __restrict__ E, const float* __restrict__ trace,
    const float* __restrict__ iW1, const float* __restrict__ ib1,
    const float* __restrict__ iW2, const float* __restrict__ ib2,
    float* __restrict__ outb)
{
    extern __shared__ float sm[];
    if (blockIdx.x < 8) {
        imp_body(blockIdx.x, sm, E, trace, iW1, ib1, iW2, ib2, outb + 2 * P_);
    } else if (blockIdx.x < 8 + NBLK) {
        pair_body<64, true>(blockIdx.x - 8, sm, g_Uc, g_Vc, cW2, cb2, cW3, cb3, lng, lnb, outb);
    } else {
        pair_body<32, false>(blockIdx.x - 8 - NBLK, sm, g_Ua, g_Va, aW2, ab2, aW3, ab3,
                             nullptr, nullptr, outb + P_);
    }
}

// ---------------- launch ----------------
extern "C" void kernel_launch(void* const* d_in, const int* in_sizes, int n_in,
                              void* d_out, int out_size)
{
    const float* E     = (const float*)d_in[0];
    const float* trace = (const float*)d_in[1];
    const float* cW1 = (const float*)d_in[2];
    const float* cb1 = (const float*)d_in[3];
    const float* lng = (const float*)d_in[4];
    const float* lnb = (const float*)d_in[5];
    const float* cW2 = (const float*)d_in[6];
    const float* cb2 = (const float*)d_in[7];
    const float* cW3 = (const float*)d_in[8];
    const float* cb3 = (const float*)d_in[9];
    const float* aW1 = (const float*)d_in[10];
    const float* ab1 = (const float*)d_in[11];
    const float* aW2 = (const float*)d_in[12];
    const float* ab2 = (const float*)d_in[13];
    const float* aW3 = (const float*)d_in[14];
    const float* ab3 = (const float*)d_in[15];
    const float* iW1 = (const float*)d_in[16];
    const float* ib1 = (const float*)d_in[17];
    const float* iW2 = (const float*)d_in[18];
    const float* ib2 = (const float*)d_in[19];
    float* out = (float*)d_out;

    cudaFuncSetAttribute(precompute_gemm_kernel, cudaFuncAttributeMaxDynamicSharedMemorySize, PRE_SMEM_BYTES);
    cudaFuncSetAttribute(pair_fused_kernel, cudaFuncAttributeMaxDynamicSharedMemorySize, SMEM_BYTES);

    precompute_gemm_kernel<<<256, 256, PRE_SMEM_BYTES>>>(E, cW1, cb1, aW1, ab1);
    pair_fused_kernel<<<8 + 2 * NBLK, 512, SMEM_BYTES>>>(
        cW2, cb2, cW3, cb3, lng, lnb, aW2, ab2, aW3, ab3,
        E, trace, iW1, ib1, iW2, ib2, out);
}

// round 10
// speedup vs baseline: 1.1191x; 1.1191x over previous
#include <cuda_runtime.h>
#include <cuda_fp16.h>
#include <math.h>
#include <stdint.h>

// ---------------- problem constants ----------------
constexpr int N_ = 1024;
constexpr int P_ = 523776;          // N*(N-1)/2
constexpr int TI = 32;              // pair tile dim
constexpr int NT = N_ / TI;         // 32 tiles per dim
constexpr int NBLK = NT * (NT + 1) / 2;  // 528 tiles over upper triangle
constexpr int UVS = 132;            // Us/Vs row stride (conflict-free float4)
constexpr int NIMP = 16;            // importance blocks (64 rows each)

// pair-kernel smem layout (per 256-thread CTA, 2 CTAs/SM)
// bytes [0, 32768):        Ht fp16 [128 rows][256 B] (XOR-swizzled 16B chunks)
// bytes [32768, 49152):    Wt fp16 [COLS<=64 rows][256 B]
constexpr int OFF_RED  = 12288;              // [512] epilogue partials / LN stats
constexpr int OFF_US   = OFF_RED + 512;      // [32][132]
constexpr int OFF_VS   = OFF_US + 32 * UVS;  // [32][132]
constexpr int OFF_B2   = OFF_VS + 32 * UVS;  // [64]
constexpr int OFF_W3   = OFF_B2 + 64;        // [64]
constexpr int OFF_LNG  = OFF_W3 + 64;        // [128]
constexpr int OFF_LNB  = OFF_LNG + 128;      // [128]
constexpr int SMEM_FLOATS = OFF_LNB + 128;
constexpr int SMEM_BYTES = SMEM_FLOATS * 4;  // ~84.5 KB  -> 2 CTAs/SM

// precompute-kernel smem
constexpr int PRE_ES_STRIDE = 132;
constexpr int PRE_WS_STRIDE = 68;
constexpr int PRE_OFF_WS = 32 * PRE_ES_STRIDE;
constexpr int PRE_SMEM_BYTES = (PRE_OFF_WS + 128 * PRE_WS_STRIDE) * 4;

// ---------------- device scratch ----------------
__device__ float g_Uc[N_ * 128];
__device__ float g_Vc[N_ * 128];
__device__ float g_Ua[N_ * 128];
__device__ float g_Va[N_ * 128];

// ---------------- helpers ----------------
__device__ __forceinline__ float gelu_f(float x) {
    float u = 0.79788456080286536f * fmaf(0.044715f * x, x * x, x);
    float th;
    asm("tanh.approx.f32 %0, %1;" : "=f"(th) : "f"(u));
    return 0.5f * x * (1.0f + th);
}
__device__ __forceinline__ float sigmoid_f(float x) {
    return 1.0f / (1.0f + expf(-x));
}
__device__ __forceinline__ uint32_t smem_u32(const void* p) {
    uint32_t a;
    asm("{ .reg .u64 t; cvta.to.shared.u64 t, %1; cvt.u32.u64 %0, t; }" : "=r"(a) : "l"(p));
    return a;
}
__device__ __forceinline__ void ldsm_x4(uint32_t& r0, uint32_t& r1, uint32_t& r2, uint32_t& r3,
                                        uint32_t addr) {
    asm volatile("ldmatrix.sync.aligned.m8n8.x4.shared.b16 {%0,%1,%2,%3}, [%4];"
                 : "=r"(r0), "=r"(r1), "=r"(r2), "=r"(r3) : "r"(addr));
}
__device__ __forceinline__ void ldsm_x2(uint32_t& r0, uint32_t& r1, uint32_t addr) {
    asm volatile("ldmatrix.sync.aligned.m8n8.x2.shared.b16 {%0,%1}, [%2];"
                 : "=r"(r0), "=r"(r1) : "r"(addr));
}
__device__ __forceinline__ void mma16816(float* c, uint32_t a0, uint32_t a1, uint32_t a2,
                                         uint32_t a3, uint32_t b0, uint32_t b1) {
    asm volatile(
        "mma.sync.aligned.m16n8k16.row.col.f32.f16.f16.f32 "
        "{%0,%1,%2,%3}, {%4,%5,%6,%7}, {%8,%9}, {%0,%1,%2,%3};"
        : "+f"(c[0]), "+f"(c[1]), "+f"(c[2]), "+f"(c[3])
        : "r"(a0), "r"(a1), "r"(a2), "r"(a3), "r"(b0), "r"(b1));
}
__device__ __forceinline__ uint4 pack8h(const float* h) {
    __half2 p0 = __floats2half2_rn(h[0], h[1]);
    __half2 p1 = __floats2half2_rn(h[2], h[3]);
    __half2 p2 = __floats2half2_rn(h[4], h[5]);
    __half2 p3 = __floats2half2_rn(h[6], h[7]);
    uint4 r;
    r.x = *reinterpret_cast<uint32_t*>(&p0);
    r.y = *reinterpret_cast<uint32_t*>(&p1);
    r.z = *reinterpret_cast<uint32_t*>(&p2);
    r.w = *reinterpret_cast<uint32_t*>(&p3);
    return r;
}

// ---------------- kernel 1: precompute tiled GEMM ----------------
__global__ void __launch_bounds__(256) precompute_gemm_kernel(
    const float* __restrict__ E,
    const float* __restrict__ cW1, const float* __restrict__ cb1,
    const float* __restrict__ aW1, const float* __restrict__ ab1)
{
    extern __shared__ float psm[];
    float* Es = psm;
    float* Ws = psm + PRE_OFF_WS;

    int rowTile = blockIdx.x >> 3;
    int colTile = blockIdx.x & 7;
    int arr = colTile >> 1;
    int c0 = (colTile & 1) * 64;
    int r0 = rowTile * 32;

    const float* Wsrc = (arr < 2) ? cW1 : aW1;
    int doff = (arr & 1) ? 128 : 0;

    int t = threadIdx.x;
    for (int x = t; x < 32 * 32; x += 256) {
        int r = x >> 5, k4 = x & 31;
        float4 e = *reinterpret_cast<const float4*>(E + (r0 + r) * 128 + k4 * 4);
        *reinterpret_cast<float4*>(Es + r * PRE_ES_STRIDE + k4 * 4) = e;
    }
    for (int x = t; x < 128 * 16; x += 256) {
        int d = x >> 4, c4 = x & 15;
        float4 w = *reinterpret_cast<const float4*>(Wsrc + (doff + d) * 128 + c0 + c4 * 4);
        *reinterpret_cast<float4*>(Ws + d * PRE_WS_STRIDE + c4 * 4) = w;
    }
    __syncthreads();

    int cgr = t & 15;
    int rg  = t >> 4;
    float acc[2][4] = {};

#pragma unroll 4
    for (int k = 0; k < 128; k += 4) {
        float4 ev[2], wv[4];
#pragma unroll
        for (int i = 0; i < 2; i++)
            ev[i] = *reinterpret_cast<const float4*>(Es + (rg * 2 + i) * PRE_ES_STRIDE + k);
#pragma unroll
        for (int kk = 0; kk < 4; kk++)
            wv[kk] = *reinterpret_cast<const float4*>(Ws + (k + kk) * PRE_WS_STRIDE + cgr * 4);
#pragma unroll
        for (int i = 0; i < 2; i++) {
            float er[4] = {ev[i].x, ev[i].y, ev[i].z, ev[i].w};
#pragma unroll
            for (int kk = 0; kk < 4; kk++) {
                acc[i][0] = fmaf(er[kk], wv[kk].x, acc[i][0]);
                acc[i][1] = fmaf(er[kk], wv[kk].y, acc[i][1]);
                acc[i][2] = fmaf(er[kk], wv[kk].z, acc[i][2]);
                acc[i][3] = fmaf(er[kk], wv[kk].w, acc[i][3]);
            }
        }
    }

    float* dst = (arr == 0) ? g_Uc : (arr == 1) ? g_Vc : (arr == 2) ? g_Ua : g_Va;
    float4 bias = make_float4(0.f, 0.f, 0.f, 0.f);
    if (arr == 0) bias = *reinterpret_cast<const float4*>(cb1 + c0 + cgr * 4);
    if (arr == 2) bias = *reinterpret_cast<const float4*>(ab1 + c0 + cgr * 4);
#pragma unroll
    for (int i = 0; i < 2; i++) {
        float4 o;
        o.x = acc[i][0] + bias.x; o.y = acc[i][1] + bias.y;
        o.z = acc[i][2] + bias.z; o.w = acc[i][3] + bias.w;
        *reinterpret_cast<float4*>(dst + (r0 + rg * 2 + i) * 128 + c0 + cgr * 4) = o;
    }
}

// ---------------- importance body (blocks 0..15, 64 rows each) ----------------
__device__ __forceinline__ void imp_body(
    int bid, float* sm,
    const float* __restrict__ E, const float* __restrict__ trace,
    const float* __restrict__ iW1, const float* __restrict__ ib1,
    const float* __restrict__ iW2, const float* __restrict__ ib2,
    float* __restrict__ outb)
{
    int t = threadIdx.x;
    float* Ws = sm;                        // [133][64]
    for (int x = t; x < 133 * 64; x += 256) Ws[x] = iW1[x];
    __syncthreads();

    int row = bid * 64 + (t >> 2);
    int c0 = (t & 3) * 16;
    float acc[16];
#pragma unroll
    for (int i = 0; i < 16; i++) acc[i] = ib1[c0 + i];

    const float* erow = E + row * 128;
    for (int d4 = 0; d4 < 32; d4++) {
        float4 e4 = *reinterpret_cast<const float4*>(erow + d4 * 4);
        float ev[4] = {e4.x, e4.y, e4.z, e4.w};
#pragma unroll
        for (int dd = 0; dd < 4; dd++) {
            const float* wrow = Ws + (d4 * 4 + dd) * 64 + c0;
            float4 w0 = *reinterpret_cast<const float4*>(wrow);
            float4 w1 = *reinterpret_cast<const float4*>(wrow + 4);
            float4 w2 = *reinterpret_cast<const float4*>(wrow + 8);
            float4 w3 = *reinterpret_cast<const float4*>(wrow + 12);
            float e = ev[dd];
            acc[0]  = fmaf(e, w0.x, acc[0]);  acc[1]  = fmaf(e, w0.y, acc[1]);
            acc[2]  = fmaf(e, w0.z, acc[2]);  acc[3]  = fmaf(e, w0.w, acc[3]);
            acc[4]  = fmaf(e, w1.x, acc[4]);  acc[5]  = fmaf(e, w1.y, acc[5]);
            acc[6]  = fmaf(e, w1.z, acc[6]);  acc[7]  = fmaf(e, w1.w, acc[7]);
            acc[8]  = fmaf(e, w2.x, acc[8]);  acc[9]  = fmaf(e, w2.y, acc[9]);
            acc[10] = fmaf(e, w2.z, acc[10]); acc[11] = fmaf(e, w2.w, acc[11]);
            acc[12] = fmaf(e, w3.x, acc[12]); acc[13] = fmaf(e, w3.y, acc[13]);
            acc[14] = fmaf(e, w3.z, acc[14]); acc[15] = fmaf(e, w3.w, acc[15]);
        }
    }
    for (int d5 = 0; d5 < 5; d5++) {
        float e = trace[row * 5 + d5];
        const float* wrow = Ws + (128 + d5) * 64 + c0;
#pragma unroll
        for (int i = 0; i < 16; i++) acc[i] = fmaf(e, wrow[i], acc[i]);
    }
    float part = 0.f;
#pragma unroll
    for (int i = 0; i < 16; i++) part = fmaf(gelu_f(acc[i]), iW2[c0 + i], part);
    part += __shfl_xor_sync(0xffffffffu, part, 1);
    part += __shfl_xor_sync(0xffffffffu, part, 2);
    if ((t & 3) == 0) outb[row] = sigmoid_f(part + ib2[0]);
}

// ---------------- pair MLP body (256 threads, 128-pair chunks, 8 chunks) ----------------
// Phase A: 2 threads/pair (broadcast-u / distinct-v), smem LN stats.
// Phase B: 8 warps, warp tile M=64 x N=COLS/4 (2 m-ranges x 4 n-ranges).
template <int COLS, bool IS_CONS>
__device__ __forceinline__ void pair_body(
    int bid, float* sm,
    const float* __restrict__ Ug, const float* __restrict__ Vg,
    const float* __restrict__ W2g, const float* __restrict__ b2g,
    const float* __restrict__ w3g, const float* __restrict__ b3g,
    const float* __restrict__ lng, const float* __restrict__ lnb,
    float* __restrict__ outb)
{
    constexpr int NW = COLS / 4;       // cols per warp (16 / 8)
    constexpr int NTL = NW / 8;        // n-tiles per warp (2 / 1)

    float* red  = sm + OFF_RED;        // [512] partials / LN stats
    float* Us   = sm + OFF_US;
    float* Vs   = sm + OFF_VS;
    float* b2s  = sm + OFF_B2;
    float* w3s  = sm + OFF_W3;
    float* lngs = sm + OFF_LNG;
    float* lnbs = sm + OFF_LNB;
    char*  smc  = reinterpret_cast<char*>(sm);
    uint32_t base_u32 = smem_u32(sm);
    uint32_t WBASE = base_u32 + 32768;

    int t = threadIdx.x;
    int wid = t >> 5;
    int lane = t & 31;

    // decode bid -> (ti, tj), tj >= ti
    int rem = bid, ti = 0;
    while (rem >= NT - ti) { rem -= NT - ti; ti++; }
    int tj = ti + rem;
    int I0 = ti * TI, J0 = tj * TI;

    // ---- one-time smem fills ----
    for (int x = t; x < COLS * 16; x += 256) {
        int n = x >> 4, j = x & 15;
        float w[8];
#pragma unroll
        for (int kk = 0; kk < 8; kk++) w[kk] = W2g[(j * 8 + kk) * COLS + n];
        uint4 pk = pack8h(w);
        *reinterpret_cast<uint4*>(smc + 32768 + n * 256 + ((j ^ (n & 7)) << 4)) = pk;
    }
    if (t < COLS) { b2s[t] = b2g[t]; w3s[t] = w3g[t]; }
    if constexpr (IS_CONS) {
        if (t >= 64 && t < 192) { lngs[t - 64] = lng[t - 64]; lnbs[t - 64] = lnb[t - 64]; }
    }
    for (int x = t; x < 32 * 128; x += 256) {
        int r = x >> 7, k = x & 127;
        Us[r * UVS + k] = Ug[(I0 + r) * 128 + k];
        Vs[r * UVS + k] = Vg[(J0 + r) * 128 + k];
    }
    float b3 = b3g[0];
    __syncthreads();

    // ---- warp GEMM decomposition ----
    int m0 = (wid & 1) * 64;
    int nrange = wid >> 1;               // 0..3
    int n0 = nrange * NW;
    int g = lane >> 2, tid4 = lane & 3;

    // B fragments: register-resident
    uint32_t bfr[8][2 * NTL];
    if constexpr (NTL == 2) {
        int nb = n0 + ((lane >> 4) & 1) * 8 + (lane & 7);
#pragma unroll
        for (int s = 0; s < 8; s++) {
            uint32_t addr = WBASE + nb * 256 +
                            (((2 * s + ((lane >> 3) & 1)) ^ (lane & 7)) << 4);
            ldsm_x4(bfr[s][0], bfr[s][1], bfr[s][2], bfr[s][3], addr);
        }
    } else {
        int nb = n0 + (lane & 7);
#pragma unroll
        for (int s = 0; s < 8; s++) {
            uint32_t addr = WBASE + nb * 256 +
                            (((2 * s + ((lane >> 3) & 1)) ^ (lane & 7)) << 4);
            ldsm_x2(bfr[s][0], bfr[s][1], addr);
        }
    }

    int roff = ((lane >> 3) & 1) * 8 + (lane & 7);
    uint32_t a_row_base = base_u32 + (m0 + roff) * 256;
    uint32_t a_sw[8];
#pragma unroll
    for (int s = 0; s < 8; s++)
        a_sw[s] = (uint32_t)(((2 * s + (lane >> 4)) ^ (lane & 7)) << 4);

    // ---- phase A decomposition ----
    int p    = t & 127;
    int half = t >> 7;
    int k0   = half * 64;
    uint32_t st_base = (uint32_t)(p * 256);
    const float* vrow = Vs + (p & 31) * UVS + k0;

    for (int cch = 0; cch < 8; cch++) {
        const float* urow = Us + (cch * 4 + (p >> 5)) * UVS + k0;

        // ---- phase A: hidden vector -> fp16 Ht ----
        if constexpr (IS_CONS) {
            float s1 = 0.f, s2 = 0.f;
#pragma unroll
            for (int kk = 0; kk < 16; kk++) {
                float4 uu = *reinterpret_cast<const float4*>(urow + kk * 4);
                float4 vv = *reinterpret_cast<const float4*>(vrow + kk * 4);
                float x0 = uu.x + vv.x, x1 = uu.y + vv.y;
                float x2 = uu.z + vv.z, x3 = uu.w + vv.w;
                s1 += (x0 + x1) + (x2 + x3);
                s2 = fmaf(x0, x0, s2); s2 = fmaf(x1, x1, s2);
                s2 = fmaf(x2, x2, s2); s2 = fmaf(x3, x3, s2);
            }
            red[half * 256 + p]       = s1;
            red[half * 256 + 128 + p] = s2;
            __syncthreads();
            float s1t = red[p] + red[256 + p];
            float s2t = red[128 + p] + red[384 + p];
            float mean = s1t * 0.0078125f;
            float var  = s2t * 0.0078125f - mean * mean;
            float rstd = rsqrtf(var + 1e-5f);
#pragma unroll
            for (int j = 0; j < 8; j++) {
                float4 uu0 = *reinterpret_cast<const float4*>(urow + j * 8);
                float4 vv0 = *reinterpret_cast<const float4*>(vrow + j * 8);
                float4 uu1 = *reinterpret_cast<const float4*>(urow + j * 8 + 4);
                float4 vv1 = *reinterpret_cast<const float4*>(vrow + j * 8 + 4);
                float xs[8] = {uu0.x + vv0.x, uu0.y + vv0.y, uu0.z + vv0.z, uu0.w + vv0.w,
                               uu1.x + vv1.x, uu1.y + vv1.y, uu1.z + vv1.z, uu1.w + vv1.w};
                float hs[8];
#pragma unroll
                for (int i2 = 0; i2 < 8; i2++) {
                    int k = k0 + j * 8 + i2;
                    float hn = fmaf((xs[i2] - mean) * rstd, lngs[k], lnbs[k]);
                    hs[i2] = gelu_f(hn);
                }
                uint4 pk = pack8h(hs);
                *reinterpret_cast<uint4*>(
                    smc + st_base + (((half * 8 + j) ^ (p & 7)) << 4)) = pk;
            }
        } else {
#pragma unroll
            for (int j = 0; j < 8; j++) {
                float4 uu0 = *reinterpret_cast<const float4*>(urow + j * 8);
                float4 vv0 = *reinterpret_cast<const float4*>(vrow + j * 8);
                float4 uu1 = *reinterpret_cast<const float4*>(urow + j * 8 + 4);
                float4 vv1 = *reinterpret_cast<const float4*>(vrow + j * 8 + 4);
                float hs[8] = {fmaxf(uu0.x + vv0.x, 0.f), fmaxf(uu0.y + vv0.y, 0.f),
                               fmaxf(uu0.z + vv0.z, 0.f), fmaxf(uu0.w + vv0.w, 0.f),
                               fmaxf(uu1.x + vv1.x, 0.f), fmaxf(uu1.y + vv1.y, 0.f),
                               fmaxf(uu1.z + vv1.z, 0.f), fmaxf(uu1.w + vv1.w, 0.f)};
                uint4 pk = pack8h(hs);
                *reinterpret_cast<uint4*>(
                    smc + st_base + (((half * 8 + j) ^ (p & 7)) << 4)) = pk;
            }
        }
        __syncthreads();

        // ---- phase B: mma.sync GEMM (all 8 warps) ----
        float acc[4][NTL][4];
#pragma unroll
        for (int mt = 0; mt < 4; mt++)
#pragma unroll
            for (int nt = 0; nt < NTL; nt++)
#pragma unroll
                for (int q = 0; q < 4; q++) acc[mt][nt][q] = 0.f;

#pragma unroll
        for (int s = 0; s < 8; s++) {
#pragma unroll
            for (int mt = 0; mt < 4; mt++) {
                uint32_t a0, a1, a2, a3;
                ldsm_x4(a0, a1, a2, a3, a_row_base + mt * 4096 + a_sw[s]);
                mma16816(acc[mt][0], a0, a1, a2, a3, bfr[s][0], bfr[s][1]);
                if constexpr (NTL == 2)
                    mma16816(acc[mt][1], a0, a1, a2, a3, bfr[s][2], bfr[s][3]);
            }
        }

        // ---- epilogue: bias + act + w3 dot, quad reduce, smem partials ----
#pragma unroll
        for (int mt = 0; mt < 4; mt++) {
            float pr0 = 0.f, pr1 = 0.f;
#pragma unroll
            for (int nt = 0; nt < NTL; nt++) {
                int c0 = n0 + nt * 8 + 2 * tid4;
                float w30 = w3s[c0], w31 = w3s[c0 + 1];
                float bb0 = b2s[c0], bb1 = b2s[c0 + 1];
                float y00 = acc[mt][nt][0] + bb0;
                float y01 = acc[mt][nt][1] + bb1;
                float y10 = acc[mt][nt][2] + bb0;
                float y11 = acc[mt][nt][3] + bb1;
                if constexpr (IS_CONS) {
                    pr0 = fmaf(gelu_f(y00), w30, pr0);
                    pr0 = fmaf(gelu_f(y01), w31, pr0);
                    pr1 = fmaf(gelu_f(y10), w30, pr1);
                    pr1 = fmaf(gelu_f(y11), w31, pr1);
                } else {
                    pr0 = fmaf(fmaxf(y00, 0.f), w30, pr0);
                    pr0 = fmaf(fmaxf(y01, 0.f), w31, pr0);
                    pr1 = fmaf(fmaxf(y10, 0.f), w30, pr1);
                    pr1 = fmaf(fmaxf(y11, 0.f), w31, pr1);
                }
            }
            pr0 += __shfl_xor_sync(0xffffffffu, pr0, 1);
            pr0 += __shfl_xor_sync(0xffffffffu, pr0, 2);
            pr1 += __shfl_xor_sync(0xffffffffu, pr1, 1);
            pr1 += __shfl_xor_sync(0xffffffffu, pr1, 2);
            if (tid4 == 0) {
                red[nrange * 128 + m0 + mt * 16 + g]     = pr0;
                red[nrange * 128 + m0 + mt * 16 + 8 + g] = pr1;
            }
        }
        __syncthreads();

        // ---- final: combine 4 n-ranges + sigmoid + triu-packed store ----
        if (t < 128) {
            float logit = b3 + ((red[t] + red[128 + t]) + (red[256 + t] + red[384 + t]));
            int i = I0 + cch * 4 + (t >> 5), j = J0 + (t & 31);
            if (i < j) {
                int pidx = i * (N_ - 1) - (i * (i - 1)) / 2 + (j - i - 1);
                outb[pidx] = sigmoid_f(logit);
            }
        }
        __syncthreads();   // red/Ht free for next chunk
    }
}

// ---------------- fused kernel: imp [0,16), cons [16,544), assoc [544,1072) ----------------
__global__ void __launch_bounds__(256, 2) pair_fused_kernel(
    const float* __restrict__ cW2, const float* __restrict__ cb2,
    const float* __restrict__ cW3, const float* __restrict__ cb3,
    const float* __restrict__ lng, const float* __restrict__ lnb,
    const float* __restrict__ aW2, const float* __restrict__ ab2,
    const float* __restrict__ aW3, const float* __restrict__ ab3,
    const float* __restrict__ E, const float* __restrict__ trace,
    const float* __restrict__ iW1, const float* __restrict__ ib1,
    const float* __restrict__ iW2, const float* __restrict__ ib2,
    float* __restrict__ outb)
{
    extern __shared__ float sm[];
    if (blockIdx.x < NIMP) {
        imp_body(blockIdx.x, sm, E, trace, iW1, ib1, iW2, ib2, outb + 2 * P_);
    } else if (blockIdx.x < NIMP + NBLK) {
        pair_body<64, true>(blockIdx.x - NIMP, sm, g_Uc, g_Vc, cW2, cb2, cW3, cb3, lng, lnb, outb);
    } else {
        pair_body<32, false>(blockIdx.x - NIMP - NBLK, sm, g_Ua, g_Va, aW2, ab2, aW3, ab3,
                             nullptr, nullptr, outb + P_);
    }
}

// ---------------- launch ----------------
extern "C" void kernel_launch(void* const* d_in, const int* in_sizes, int n_in,
                              void* d_out, int out_size)
{
    const float* E     = (const float*)d_in[0];
    const float* trace = (const float*)d_in[1];
    const float* cW1 = (const float*)d_in[2];
    const float* cb1 = (const float*)d_in[3];
    const float* lng = (const float*)d_in[4];
    const float* lnb = (const float*)d_in[5];
    const float* cW2 = (const float*)d_in[6];
    const float* cb2 = (const float*)d_in[7];
    const float* cW3 = (const float*)d_in[8];
    const float* cb3 = (const float*)d_in[9];
    const float* aW1 = (const float*)d_in[10];
    const float* ab1 = (const float*)d_in[11];
    const float* aW2 = (const float*)d_in[12];
    const float* ab2 = (const float*)d_in[13];
    const float* aW3 = (const float*)d_in[14];
    const float* ab3 = (const float*)d_in[15];
    const float* iW1 = (const float*)d_in[16];
    const float* ib1 = (const float*)d_in[17];
    const float* iW2 = (const float*)d_in[18];
    const float* ib2 = (const float*)d_in[19];
    float* out = (float*)d_out;

    cudaFuncSetAttribute(precompute_gemm_kernel, cudaFuncAttributeMaxDynamicSharedMemorySize, PRE_SMEM_BYTES);
    cudaFuncSetAttribute(pair_fused_kernel, cudaFuncAttributeMaxDynamicSharedMemorySize, SMEM_BYTES);

    precompute_gemm_kernel<<<256, 256, PRE_SMEM_BYTES>>>(E, cW1, cb1, aW1, ab1);
    pair_fused_kernel<<<NIMP + 2 * NBLK, 256, SMEM_BYTES>>>(
        cW2, cb2, cW3, cb3, lng, lnb, aW2, ab2, aW3, ab3,
        E, trace, iW1, ib1, iW2, ib2, out);
}

// round 11
// speedup vs baseline: 1.3185x; 1.1782x over previous
#include <cuda_runtime.h>
#include <cuda_fp16.h>
#include <math.h>
#include <stdint.h>

// ---------------- problem constants ----------------
constexpr int N_ = 1024;
constexpr int P_ = 523776;          // N*(N-1)/2
constexpr int TI = 32;              // pair tile dim
constexpr int NT = N_ / TI;         // 32 tiles per dim
constexpr int NBLK = NT * (NT + 1) / 2;  // 528 tiles over upper triangle
constexpr int NIMP = 16;            // importance blocks (64 rows each)

// pair-kernel smem layout (per 256-thread CTA, 2 CTAs/SM)
// bytes [0, 32768):      Ht fp16 [128 rows][256 B]  (XOR-swizzled 16B chunks)
// bytes [32768, 49152):  Wt fp16 [COLS<=64 rows][256 B]
// bytes [49152, 57344):  Uh fp16 [32 rows][256 B]
// bytes [57344, 65536):  Vh fp16 [32 rows][256 B]
constexpr int WT_BASE = 32768;
constexpr int UH_BASE = 49152;
constexpr int VH_BASE = 57344;
constexpr int OFF_RED = 16384;               // [512] epilogue partials
constexpr int OFF_D   = OFF_RED + 512;       // [1024] D = U.V^T
constexpr int OFF_SQ  = OFF_D + 1024;        // [128]  S[64], Q[64]
constexpr int OFF_B2  = OFF_SQ + 128;        // [64]
constexpr int OFF_W3  = OFF_B2 + 64;         // [64]
constexpr int OFF_LNG = OFF_W3 + 64;         // [128]
constexpr int OFF_LNB = OFF_LNG + 128;       // [128]
constexpr int SMEM_FLOATS = OFF_LNB + 128;
constexpr int SMEM_BYTES = SMEM_FLOATS * 4;  // ~73.5 KB -> 2 CTAs/SM

// precompute-kernel smem
constexpr int PRE_ES_STRIDE = 132;
constexpr int PRE_WS_STRIDE = 68;
constexpr int PRE_OFF_WS = 32 * PRE_ES_STRIDE;
constexpr int PRE_SMEM_BYTES = (PRE_OFF_WS + 128 * PRE_WS_STRIDE) * 4;

// ---------------- device scratch ----------------
__device__ float g_Uc[N_ * 128];
__device__ float g_Vc[N_ * 128];
__device__ float g_Ua[N_ * 128];
__device__ float g_Va[N_ * 128];

// ---------------- helpers ----------------
__device__ __forceinline__ float gelu_f(float x) {
    float u = 0.79788456080286536f * fmaf(0.044715f * x, x * x, x);
    float th;
    asm("tanh.approx.f32 %0, %1;" : "=f"(th) : "f"(u));
    return 0.5f * x * (1.0f + th);
}
__device__ __forceinline__ float sigmoid_f(float x) {
    return 1.0f / (1.0f + expf(-x));
}
__device__ __forceinline__ uint32_t smem_u32(const void* p) {
    uint32_t a;
    asm("{ .reg .u64 t; cvta.to.shared.u64 t, %1; cvt.u32.u64 %0, t; }" : "=r"(a) : "l"(p));
    return a;
}
__device__ __forceinline__ void ldsm_x4(uint32_t& r0, uint32_t& r1, uint32_t& r2, uint32_t& r3,
                                        uint32_t addr) {
    asm volatile("ldmatrix.sync.aligned.m8n8.x4.shared.b16 {%0,%1,%2,%3}, [%4];"
                 : "=r"(r0), "=r"(r1), "=r"(r2), "=r"(r3) : "r"(addr));
}
__device__ __forceinline__ void ldsm_x2(uint32_t& r0, uint32_t& r1, uint32_t addr) {
    asm volatile("ldmatrix.sync.aligned.m8n8.x2.shared.b16 {%0,%1}, [%2];"
                 : "=r"(r0), "=r"(r1) : "r"(addr));
}
__device__ __forceinline__ void mma16816(float* c, uint32_t a0, uint32_t a1, uint32_t a2,
                                         uint32_t a3, uint32_t b0, uint32_t b1) {
    asm volatile(
        "mma.sync.aligned.m16n8k16.row.col.f32.f16.f16.f32 "
        "{%0,%1,%2,%3}, {%4,%5,%6,%7}, {%8,%9}, {%0,%1,%2,%3};"
        : "+f"(c[0]), "+f"(c[1]), "+f"(c[2]), "+f"(c[3])
        : "r"(a0), "r"(a1), "r"(a2), "r"(a3), "r"(b0), "r"(b1));
}
__device__ __forceinline__ uint4 pack8h(const float* h) {
    __half2 p0 = __floats2half2_rn(h[0], h[1]);
    __half2 p1 = __floats2half2_rn(h[2], h[3]);
    __half2 p2 = __floats2half2_rn(h[4], h[5]);
    __half2 p3 = __floats2half2_rn(h[6], h[7]);
    uint4 r;
    r.x = *reinterpret_cast<uint32_t*>(&p0);
    r.y = *reinterpret_cast<uint32_t*>(&p1);
    r.z = *reinterpret_cast<uint32_t*>(&p2);
    r.w = *reinterpret_cast<uint32_t*>(&p3);
    return r;
}
__device__ __forceinline__ void unpack8h(uint4 q, float* f) {
    const __half2* h = reinterpret_cast<const __half2*>(&q);
#pragma unroll
    for (int i = 0; i < 4; i++) {
        float2 f2 = __half22float2(h[i]);
        f[2 * i] = f2.x; f[2 * i + 1] = f2.y;
    }
}

// ---------------- kernel 1: precompute tiled GEMM ----------------
__global__ void __launch_bounds__(256) precompute_gemm_kernel(
    const float* __restrict__ E,
    const float* __restrict__ cW1, const float* __restrict__ cb1,
    const float* __restrict__ aW1, const float* __restrict__ ab1)
{
    extern __shared__ float psm[];
    float* Es = psm;
    float* Ws = psm + PRE_OFF_WS;

    int rowTile = blockIdx.x >> 3;
    int colTile = blockIdx.x & 7;
    int arr = colTile >> 1;
    int c0 = (colTile & 1) * 64;
    int r0 = rowTile * 32;

    const float* Wsrc = (arr < 2) ? cW1 : aW1;
    int doff = (arr & 1) ? 128 : 0;

    int t = threadIdx.x;
    for (int x = t; x < 32 * 32; x += 256) {
        int r = x >> 5, k4 = x & 31;
        float4 e = *reinterpret_cast<const float4*>(E + (r0 + r) * 128 + k4 * 4);
        *reinterpret_cast<float4*>(Es + r * PRE_ES_STRIDE + k4 * 4) = e;
    }
    for (int x = t; x < 128 * 16; x += 256) {
        int d = x >> 4, c4 = x & 15;
        float4 w = *reinterpret_cast<const float4*>(Wsrc + (doff + d) * 128 + c0 + c4 * 4);
        *reinterpret_cast<float4*>(Ws + d * PRE_WS_STRIDE + c4 * 4) = w;
    }
    __syncthreads();

    int cgr = t & 15;
    int rg  = t >> 4;
    float acc[2][4] = {};

#pragma unroll 4
    for (int k = 0; k < 128; k += 4) {
        float4 ev[2], wv[4];
#pragma unroll
        for (int i = 0; i < 2; i++)
            ev[i] = *reinterpret_cast<const float4*>(Es + (rg * 2 + i) * PRE_ES_STRIDE + k);
#pragma unroll
        for (int kk = 0; kk < 4; kk++)
            wv[kk] = *reinterpret_cast<const float4*>(Ws + (k + kk) * PRE_WS_STRIDE + cgr * 4);
#pragma unroll
        for (int i = 0; i < 2; i++) {
            float er[4] = {ev[i].x, ev[i].y, ev[i].z, ev[i].w};
#pragma unroll
            for (int kk = 0; kk < 4; kk++) {
                acc[i][0] = fmaf(er[kk], wv[kk].x, acc[i][0]);
                acc[i][1] = fmaf(er[kk], wv[kk].y, acc[i][1]);
                acc[i][2] = fmaf(er[kk], wv[kk].z, acc[i][2]);
                acc[i][3] = fmaf(er[kk], wv[kk].w, acc[i][3]);
            }
        }
    }

    float* dst = (arr == 0) ? g_Uc : (arr == 1) ? g_Vc : (arr == 2) ? g_Ua : g_Va;
    float4 bias = make_float4(0.f, 0.f, 0.f, 0.f);
    if (arr == 0) bias = *reinterpret_cast<const float4*>(cb1 + c0 + cgr * 4);
    if (arr == 2) bias = *reinterpret_cast<const float4*>(ab1 + c0 + cgr * 4);
#pragma unroll
    for (int i = 0; i < 2; i++) {
        float4 o;
        o.x = acc[i][0] + bias.x; o.y = acc[i][1] + bias.y;
        o.z = acc[i][2] + bias.z; o.w = acc[i][3] + bias.w;
        *reinterpret_cast<float4*>(dst + (r0 + rg * 2 + i) * 128 + c0 + cgr * 4) = o;
    }
}

// ---------------- importance body (blocks 0..15, 64 rows each) ----------------
__device__ __forceinline__ void imp_body(
    int bid, float* sm,
    const float* __restrict__ E, const float* __restrict__ trace,
    const float* __restrict__ iW1, const float* __restrict__ ib1,
    const float* __restrict__ iW2, const float* __restrict__ ib2,
    float* __restrict__ outb)
{
    int t = threadIdx.x;
    float* Ws = sm;                        // [133][64]
    for (int x = t; x < 133 * 64; x += 256) Ws[x] = iW1[x];
    __syncthreads();

    int row = bid * 64 + (t >> 2);
    int c0 = (t & 3) * 16;
    float acc[16];
#pragma unroll
    for (int i = 0; i < 16; i++) acc[i] = ib1[c0 + i];

    const float* erow = E + row * 128;
    for (int d4 = 0; d4 < 32; d4++) {
        float4 e4 = *reinterpret_cast<const float4*>(erow + d4 * 4);
        float ev[4] = {e4.x, e4.y, e4.z, e4.w};
#pragma unroll
        for (int dd = 0; dd < 4; dd++) {
            const float* wrow = Ws + (d4 * 4 + dd) * 64 + c0;
            float4 w0 = *reinterpret_cast<const float4*>(wrow);
            float4 w1 = *reinterpret_cast<const float4*>(wrow + 4);
            float4 w2 = *reinterpret_cast<const float4*>(wrow + 8);
            float4 w3 = *reinterpret_cast<const float4*>(wrow + 12);
            float e = ev[dd];
            acc[0]  = fmaf(e, w0.x, acc[0]);  acc[1]  = fmaf(e, w0.y, acc[1]);
            acc[2]  = fmaf(e, w0.z, acc[2]);  acc[3]  = fmaf(e, w0.w, acc[3]);
            acc[4]  = fmaf(e, w1.x, acc[4]);  acc[5]  = fmaf(e, w1.y, acc[5]);
            acc[6]  = fmaf(e, w1.z, acc[6]);  acc[7]  = fmaf(e, w1.w, acc[7]);
            acc[8]  = fmaf(e, w2.x, acc[8]);  acc[9]  = fmaf(e, w2.y, acc[9]);
            acc[10] = fmaf(e, w2.z, acc[10]); acc[11] = fmaf(e, w2.w, acc[11]);
            acc[12] = fmaf(e, w3.x, acc[12]); acc[13] = fmaf(e, w3.y, acc[13]);
            acc[14] = fmaf(e, w3.z, acc[14]); acc[15] = fmaf(e, w3.w, acc[15]);
        }
    }
    for (int d5 = 0; d5 < 5; d5++) {
        float e = trace[row * 5 + d5];
        const float* wrow = Ws + (128 + d5) * 64 + c0;
#pragma unroll
        for (int i = 0; i < 16; i++) acc[i] = fmaf(e, wrow[i], acc[i]);
    }
    float part = 0.f;
#pragma unroll
    for (int i = 0; i < 16; i++) part = fmaf(gelu_f(acc[i]), iW2[c0 + i], part);
    part += __shfl_xor_sync(0xffffffffu, part, 1);
    part += __shfl_xor_sync(0xffffffffu, part, 2);
    if ((t & 3) == 0) outb[row] = sigmoid_f(part + ib2[0]);
}

// ---------------- pair MLP body ----------------
// 256 threads, 8 chunks of 128 pairs. Phase A: fp16 u/v reads, LN stats from
// precomputed S/Q tables + D = U.V^T (one-time 32x32x128 mma). Phase B: 8 warps
// mma.sync, B fragments register-resident. 2 barriers per chunk.
template <int COLS, bool IS_CONS>
__device__ __forceinline__ void pair_body(
    int bid, float* sm,
    const float* __restrict__ Ug, const float* __restrict__ Vg,
    const float* __restrict__ W2g, const float* __restrict__ b2g,
    const float* __restrict__ w3g, const float* __restrict__ b3g,
    const float* __restrict__ lng, const float* __restrict__ lnb,
    float* __restrict__ outb)
{
    constexpr int NW = COLS / 4;       // cols per warp (16 / 8)
    constexpr int NTL = NW / 8;        // n-tiles per warp (2 / 1)

    float* red  = sm + OFF_RED;
    float* Ds   = sm + OFF_D;
    float* SQ   = sm + OFF_SQ;
    float* b2s  = sm + OFF_B2;
    float* w3s  = sm + OFF_W3;
    float* lngs = sm + OFF_LNG;
    float* lnbs = sm + OFF_LNB;
    char*  smc  = reinterpret_cast<char*>(sm);
    uint32_t base_u32 = smem_u32(sm);

    int t = threadIdx.x;
    int wid = t >> 5;
    int lane = t & 31;

    // decode bid -> (ti, tj), tj >= ti
    int rem = bid, ti = 0;
    while (rem >= NT - ti) { rem -= NT - ti; ti++; }
    int tj = ti + rem;
    int I0 = ti * TI, J0 = tj * TI;

    // ---- one-time smem fills ----
    // Wt fp16 [COLS][128k]
    for (int x = t; x < COLS * 16; x += 256) {
        int n = x >> 4, j = x & 15;
        float w[8];
#pragma unroll
        for (int kk = 0; kk < 8; kk++) w[kk] = W2g[(j * 8 + kk) * COLS + n];
        uint4 pk = pack8h(w);
        *reinterpret_cast<uint4*>(smc + WT_BASE + n * 256 + ((j ^ (n & 7)) << 4)) = pk;
    }
    if (t < COLS) { b2s[t] = b2g[t]; w3s[t] = w3g[t]; }
    if constexpr (IS_CONS) {
        if (t >= 64 && t < 192) { lngs[t - 64] = lng[t - 64]; lnbs[t - 64] = lnb[t - 64]; }
    }
    // Uh/Vh fp16 from global
    for (int x = t; x < 64 * 16; x += 256) {
        int r = x >> 4, j = x & 15;
        const float* src = (r < 32) ? (Ug + (I0 + r) * 128 + j * 8)
                                    : (Vg + (J0 + (r - 32)) * 128 + j * 8);
        float w[8];
        float4 a0 = *reinterpret_cast<const float4*>(src);
        float4 a1 = *reinterpret_cast<const float4*>(src + 4);
        w[0] = a0.x; w[1] = a0.y; w[2] = a0.z; w[3] = a0.w;
        w[4] = a1.x; w[5] = a1.y; w[6] = a1.z; w[7] = a1.w;
        uint4 pk = pack8h(w);
        uint32_t boff = ((r < 32) ? UH_BASE : VH_BASE) + (r & 31) * 256 + ((j ^ (r & 7)) << 4);
        *reinterpret_cast<uint4*>(smc + boff) = pk;
    }
    // S/Q tables (cons only): exact f32 row sums / sumsq from global
    if constexpr (IS_CONS) {
        int r = t >> 2, q = t & 3;
        const float* src = (r < 32) ? (Ug + (I0 + r) * 128) : (Vg + (J0 + (r - 32)) * 128);
        float S = 0.f, Q = 0.f;
#pragma unroll
        for (int kk = 0; kk < 8; kk++) {
            float4 a = *reinterpret_cast<const float4*>(src + q * 32 + kk * 4);
            S += (a.x + a.y) + (a.z + a.w);
            Q = fmaf(a.x, a.x, Q); Q = fmaf(a.y, a.y, Q);
            Q = fmaf(a.z, a.z, Q); Q = fmaf(a.w, a.w, Q);
        }
        S += __shfl_xor_sync(0xffffffffu, S, 1);
        Q += __shfl_xor_sync(0xffffffffu, Q, 1);
        S += __shfl_xor_sync(0xffffffffu, S, 2);
        Q += __shfl_xor_sync(0xffffffffu, Q, 2);
        if (q == 0) { SQ[r] = S; SQ[64 + r] = Q; }
    }
    float b3 = b3g[0];
    __syncthreads();

    // ---- one-time D = U.V^T (cons only): 32x32x128 via 8 warps ----
    if constexpr (IS_CONS) {
        int mt = wid & 1, ntd = wid >> 1;
        int roffd = ((lane >> 3) & 1) * 8 + (lane & 7);
        uint32_t aab = base_u32 + UH_BASE + (mt * 16 + roffd) * 256;
        uint32_t bbb = base_u32 + VH_BASE + (ntd * 8 + (lane & 7)) * 256;
        float c[4] = {0.f, 0.f, 0.f, 0.f};
#pragma unroll
        for (int s = 0; s < 8; s++) {
            uint32_t a0, a1, a2, a3, b0, b1;
            ldsm_x4(a0, a1, a2, a3, aab + (((2 * s + (lane >> 4)) ^ (lane & 7)) << 4));
            ldsm_x2(b0, b1, bbb + (((2 * s + ((lane >> 3) & 1)) ^ (lane & 7)) << 4));
            mma16816(c, a0, a1, a2, a3, b0, b1);
        }
        int g2 = lane >> 2, t4 = lane & 3;
        float* Dp = Ds + (mt * 16 + g2) * 32 + ntd * 8 + 2 * t4;
        Dp[0] = c[0]; Dp[1] = c[1];
        Dp[8 * 32] = c[2]; Dp[8 * 32 + 1] = c[3];
        __syncthreads();
    }

    // ---- warp GEMM decomposition ----
    int m0 = (wid & 1) * 64;
    int nrange = wid >> 1;               // 0..3
    int n0 = nrange * NW;
    int g = lane >> 2, tid4 = lane & 3;

    // per-thread register caches for epilogue
    float w3r[2 * NTL], b2r[2 * NTL];
#pragma unroll
    for (int nt = 0; nt < NTL; nt++) {
        int c0 = n0 + nt * 8 + 2 * tid4;
        w3r[2 * nt] = w3s[c0];     w3r[2 * nt + 1] = w3s[c0 + 1];
        b2r[2 * nt] = b2s[c0];     b2r[2 * nt + 1] = b2s[c0 + 1];
    }

    // B fragments: register-resident
    uint32_t WBASE = base_u32 + WT_BASE;
    uint32_t bfr[8][2 * NTL];
    if constexpr (NTL == 2) {
        int nb = n0 + ((lane >> 4) & 1) * 8 + (lane & 7);
#pragma unroll
        for (int s = 0; s < 8; s++) {
            uint32_t addr = WBASE + nb * 256 +
                            (((2 * s + ((lane >> 3) & 1)) ^ (lane & 7)) << 4);
            ldsm_x4(bfr[s][0], bfr[s][1], bfr[s][2], bfr[s][3], addr);
        }
    } else {
        int nb = n0 + (lane & 7);
#pragma unroll
        for (int s = 0; s < 8; s++) {
            uint32_t addr = WBASE + nb * 256 +
                            (((2 * s + ((lane >> 3) & 1)) ^ (lane & 7)) << 4);
            ldsm_x2(bfr[s][0], bfr[s][1], addr);
        }
    }

    int roff = ((lane >> 3) & 1) * 8 + (lane & 7);
    uint32_t a_row_base = base_u32 + (m0 + roff) * 256;
    uint32_t a_sw[8];
#pragma unroll
    for (int s = 0; s < 8; s++)
        a_sw[s] = (uint32_t)(((2 * s + (lane >> 4)) ^ (lane & 7)) << 4);

    // ---- phase A decomposition ----
    int p    = t & 127;
    int half = t >> 7;
    int vr   = p & 31;
    uint32_t st_base = (uint32_t)(p * 256);
    uint32_t vh_row = VH_BASE + vr * 256;

    for (int cch = 0; cch < 8; cch++) {
        // ---- combine previous chunk (reads red; no conflict with phase A) ----
        if (cch > 0 && t < 128) {
            int c = cch - 1;
            float logit = b3 + ((red[t] + red[128 + t]) + (red[256 + t] + red[384 + t]));
            int i = I0 + c * 4 + (t >> 5), j = J0 + (t & 31);
            if (i < j) {
                int pidx = i * (N_ - 1) - (i * (i - 1)) / 2 + (j - i - 1);
                outb[pidx] = sigmoid_f(logit);
            }
        }

        // ---- phase A: fp16 u/v -> h -> Ht ----
        int urow = cch * 4 + (p >> 5);
        uint32_t uh_row = UH_BASE + urow * 256;
        float mean = 0.f, rstd = 0.f, mr = 0.f;
        if constexpr (IS_CONS) {
            float Su = SQ[urow], Sv = SQ[32 + vr];
            float Qu = SQ[64 + urow], Qv = SQ[96 + vr];
            float Dv = Ds[urow * 32 + vr];
            mean = (Su + Sv) * 0.0078125f;
            float ms2 = (Qu + Qv + 2.f * Dv) * 0.0078125f;
            rstd = rsqrtf(ms2 - mean * mean + 1e-5f);
            mr = mean * rstd;
        }
#pragma unroll
        for (int j = 0; j < 8; j++) {
            int c = half * 8 + j;
            uint4 uq = *reinterpret_cast<const uint4*>(smc + uh_row + ((c ^ (urow & 7)) << 4));
            uint4 vq = *reinterpret_cast<const uint4*>(smc + vh_row + ((c ^ (vr & 7)) << 4));
            float uf[8], vf[8], hs[8];
            unpack8h(uq, uf);
            unpack8h(vq, vf);
            if constexpr (IS_CONS) {
                float4 lg0 = *reinterpret_cast<const float4*>(lngs + c * 8);
                float4 lg1 = *reinterpret_cast<const float4*>(lngs + c * 8 + 4);
                float4 lb0 = *reinterpret_cast<const float4*>(lnbs + c * 8);
                float4 lb1 = *reinterpret_cast<const float4*>(lnbs + c * 8 + 4);
                float lg[8] = {lg0.x, lg0.y, lg0.z, lg0.w, lg1.x, lg1.y, lg1.z, lg1.w};
                float lb[8] = {lb0.x, lb0.y, lb0.z, lb0.w, lb1.x, lb1.y, lb1.z, lb1.w};
#pragma unroll
                for (int i2 = 0; i2 < 8; i2++) {
                    float x = uf[i2] + vf[i2];
                    float hn = fmaf(x, rstd, -mr);          // (x - mean) * rstd
                    hn = fmaf(hn, lg[i2], lb[i2]);
                    hs[i2] = gelu_f(hn);
                }
            } else {
#pragma unroll
                for (int i2 = 0; i2 < 8; i2++)
                    hs[i2] = fmaxf(uf[i2] + vf[i2], 0.f);
            }
            uint4 pk = pack8h(hs);
            *reinterpret_cast<uint4*>(smc + st_base + ((c ^ (p & 7)) << 4)) = pk;
        }
        __syncthreads();

        // ---- phase B: mma.sync GEMM (all 8 warps) ----
        float acc[4][NTL][4];
#pragma unroll
        for (int mt = 0; mt < 4; mt++)
#pragma unroll
            for (int nt = 0; nt < NTL; nt++)
#pragma unroll
                for (int q = 0; q < 4; q++) acc[mt][nt][q] = 0.f;

#pragma unroll
        for (int s = 0; s < 8; s++) {
#pragma unroll
            for (int mt = 0; mt < 4; mt++) {
                uint32_t a0, a1, a2, a3;
                ldsm_x4(a0, a1, a2, a3, a_row_base + mt * 4096 + a_sw[s]);
                mma16816(acc[mt][0], a0, a1, a2, a3, bfr[s][0], bfr[s][1]);
                if constexpr (NTL == 2)
                    mma16816(acc[mt][1], a0, a1, a2, a3, bfr[s][2], bfr[s][3]);
            }
        }

        // ---- epilogue: bias + act + w3 dot, quad reduce, smem partials ----
#pragma unroll
        for (int mt = 0; mt < 4; mt++) {
            float pr0 = 0.f, pr1 = 0.f;
#pragma unroll
            for (int nt = 0; nt < NTL; nt++) {
                float y00 = acc[mt][nt][0] + b2r[2 * nt];
                float y01 = acc[mt][nt][1] + b2r[2 * nt + 1];
                float y10 = acc[mt][nt][2] + b2r[2 * nt];
                float y11 = acc[mt][nt][3] + b2r[2 * nt + 1];
                if constexpr (IS_CONS) {
                    pr0 = fmaf(gelu_f(y00), w3r[2 * nt], pr0);
                    pr0 = fmaf(gelu_f(y01), w3r[2 * nt + 1], pr0);
                    pr1 = fmaf(gelu_f(y10), w3r[2 * nt], pr1);
                    pr1 = fmaf(gelu_f(y11), w3r[2 * nt + 1], pr1);
                } else {
                    pr0 = fmaf(fmaxf(y00, 0.f), w3r[2 * nt], pr0);
                    pr0 = fmaf(fmaxf(y01, 0.f), w3r[2 * nt + 1], pr0);
                    pr1 = fmaf(fmaxf(y10, 0.f), w3r[2 * nt], pr1);
                    pr1 = fmaf(fmaxf(y11, 0.f), w3r[2 * nt + 1], pr1);
                }
            }
            pr0 += __shfl_xor_sync(0xffffffffu, pr0, 1);
            pr0 += __shfl_xor_sync(0xffffffffu, pr0, 2);
            pr1 += __shfl_xor_sync(0xffffffffu, pr1, 1);
            pr1 += __shfl_xor_sync(0xffffffffu, pr1, 2);
            if (tid4 == 0) {
                red[nrange * 128 + m0 + mt * 16 + g]     = pr0;
                red[nrange * 128 + m0 + mt * 16 + 8 + g] = pr1;
            }
        }
        __syncthreads();   // red visible; Ht consumed before next overwrite
    }

    // ---- final combine for chunk 7 ----
    if (t < 128) {
        float logit = b3 + ((red[t] + red[128 + t]) + (red[256 + t] + red[384 + t]));
        int i = I0 + 7 * 4 + (t >> 5), j = J0 + (t & 31);
        if (i < j) {
            int pidx = i * (N_ - 1) - (i * (i - 1)) / 2 + (j - i - 1);
            outb[pidx] = sigmoid_f(logit);
        }
    }
}

// ---------------- fused kernel: imp [0,16), cons [16,544), assoc [544,1072) ----------------
__global__ void __launch_bounds__(256, 2) pair_fused_kernel(
    const float* __restrict__ cW2, const float* __restrict__ cb2,
    const float* __restrict__ cW3, const float* __restrict__ cb3,
    const float* __restrict__ lng, const float* __restrict__ lnb,
    const float* __restrict__ aW2, const float* __restrict__ ab2,
    const float* __restrict__ aW3, const float* __restrict__ ab3,
    const float* __restrict__ E, const float* __restrict__ trace,
    const float* __restrict__ iW1, const float* __restrict__ ib1,
    const float* __restrict__ iW2, const float* __restrict__ ib2,
    float* __restrict__ outb)
{
    extern __shared__ float sm[];
    if (blockIdx.x < NIMP) {
        imp_body(blockIdx.x, sm, E, trace, iW1, ib1, iW2, ib2, outb + 2 * P_);
    } else if (blockIdx.x < NIMP + NBLK) {
        pair_body<64, true>(blockIdx.x - NIMP, sm, g_Uc, g_Vc, cW2, cb2, cW3, cb3, lng, lnb, outb);
    } else {
        pair_body<32, false>(blockIdx.x - NIMP - NBLK, sm, g_Ua, g_Va, aW2, ab2, aW3, ab3,
                             nullptr, nullptr, outb + P_);
    }
}

// ---------------- launch ----------------
extern "C" void kernel_launch(void* const* d_in, const int* in_sizes, int n_in,
                              void* d_out, int out_size)
{
    const float* E     = (const float*)d_in[0];
    const float* trace = (const float*)d_in[1];
    const float* cW1 = (const float*)d_in[2];
    const float* cb1 = (const float*)d_in[3];
    const float* lng = (const float*)d_in[4];
    const float* lnb = (const float*)d_in[5];
    const float* cW2 = (const float*)d_in[6];
    const float* cb2 = (const float*)d_in[7];
    const float* cW3 = (const float*)d_in[8];
    const float* cb3 = (const float*)d_in[9];
    const float* aW1 = (const float*)d_in[10];
    const float* ab1 = (const float*)d_in[11];
    const float* aW2 = (const float*)d_in[12];
    const float* ab2 = (const float*)d_in[13];
    const float* aW3 = (const float*)d_in[14];
    const float* ab3 = (const float*)d_in[15];
    const float* iW1 = (const float*)d_in[16];
    const float* ib1 = (const float*)d_in[17];
    const float* iW2 = (const float*)d_in[18];
    const float* ib2 = (const float*)d_in[19];
    float* out = (float*)d_out;

    cudaFuncSetAttribute(precompute_gemm_kernel, cudaFuncAttributeMaxDynamicSharedMemorySize, PRE_SMEM_BYTES);
    cudaFuncSetAttribute(pair_fused_kernel, cudaFuncAttributeMaxDynamicSharedMemorySize, SMEM_BYTES);

    precompute_gemm_kernel<<<256, 256, PRE_SMEM_BYTES>>>(E, cW1, cb1, aW1, ab1);
    pair_fused_kernel<<<NIMP + 2 * NBLK, 256, SMEM_BYTES>>>(
        cW2, cb2, cW3, cb3, lng, lnb, aW2, ab2, aW3, ab3,
        E, trace, iW1, ib1, iW2, ib2, out);
}